// round 1
// baseline (speedup 1.0000x reference)
#include <cuda_runtime.h>

#define BB 2
#define CC 64
#define CQ 8
#define NN 9216
#define NT 48
#define MT 128

// Scratch (allocation-free rule: __device__ globals)
__device__ __align__(16) float g_q[BB][NN][CQ];    // q, [b][n][d]
__device__ __align__(16) float g_k[BB][NN][CQ];    // k, [b][m][d]
__device__ __align__(16) float g_v[BB][NN][CC];    // v, scaled in place to v/Z by k_rowsum
__device__ __align__(16) float g_att[BB][CC][NN];  // att = V @ S

// ---------- packed f32x2 helpers (Blackwell FFMA2, PTX-only) ----------
static __device__ __forceinline__ unsigned long long pk2(float a, float b) {
    unsigned long long r;
    asm("mov.b64 %0, {%1, %2};" : "=l"(r)
        : "r"(__float_as_uint(a)), "r"(__float_as_uint(b)));
    return r;
}
static __device__ __forceinline__ void upk2(unsigned long long p, float& a, float& b) {
    unsigned int x, y;
    asm("mov.b64 {%0, %1}, %2;" : "=r"(x), "=r"(y) : "l"(p));
    a = __uint_as_float(x);
    b = __uint_as_float(y);
}
static __device__ __forceinline__ unsigned long long ffma2(
    unsigned long long a, unsigned long long b, unsigned long long c) {
    unsigned long long d;
    asm("fma.rn.f32x2 %0, %1, %2, %3;" : "=l"(d) : "l"(a), "l"(b), "l"(c));
    return d;
}

// ---------------------------------------------------------------------
// Kernel 1: q/k/v 1x1 convs.  128 threads = 128 pixels per block.
// ---------------------------------------------------------------------
__global__ void __launch_bounds__(128) k_qkv(
    const float* __restrict__ x,
    const float* __restrict__ wq, const float* __restrict__ bq,
    const float* __restrict__ wk, const float* __restrict__ bk,
    const float* __restrict__ wv, const float* __restrict__ bv)
{
    __shared__ float WT[CC][80];   // [c][o]: o<8 -> wq, o<16 -> wk, else wv
    __shared__ float bias[80];
    int t = threadIdx.x;
    for (int idx = t; idx < CC * 80; idx += 128) {
        int c = idx / 80, o = idx % 80;
        float w;
        if (o < 8)       w = wq[o * CC + c];
        else if (o < 16) w = wk[(o - 8) * CC + c];
        else             w = wv[(o - 16) * CC + c];
        WT[c][o] = w;
    }
    if (t < 80) bias[t] = (t < 8) ? bq[t] : (t < 16 ? bk[t - 8] : bv[t - 16]);
    __syncthreads();

    int pix = blockIdx.x * 128 + t;      // 0..18431
    int b = pix / NN, n = pix % NN;
    const float* xp = x + (size_t)b * CC * NN + n;
    float xr[CC];
#pragma unroll
    for (int c = 0; c < CC; c++) xr[c] = xp[(size_t)c * NN];   // coalesced per c

    for (int o0 = 0; o0 < 80; o0 += 8) {
        float acc[8];
#pragma unroll
        for (int j = 0; j < 8; j++) acc[j] = bias[o0 + j];
#pragma unroll 16
        for (int c = 0; c < CC; c++) {
            float4 wa = *(const float4*)&WT[c][o0];
            float4 wb = *(const float4*)&WT[c][o0 + 4];
            float xv = xr[c];
            acc[0] = fmaf(wa.x, xv, acc[0]);
            acc[1] = fmaf(wa.y, xv, acc[1]);
            acc[2] = fmaf(wa.z, xv, acc[2]);
            acc[3] = fmaf(wa.w, xv, acc[3]);
            acc[4] = fmaf(wb.x, xv, acc[4]);
            acc[5] = fmaf(wb.y, xv, acc[5]);
            acc[6] = fmaf(wb.z, xv, acc[6]);
            acc[7] = fmaf(wb.w, xv, acc[7]);
        }
        float4 r0 = make_float4(acc[0], acc[1], acc[2], acc[3]);
        float4 r1 = make_float4(acc[4], acc[5], acc[6], acc[7]);
        if (o0 == 0) {
            *(float4*)&g_q[b][n][0] = r0;
            *(float4*)&g_q[b][n][4] = r1;
        } else if (o0 == 8) {
            *(float4*)&g_k[b][n][0] = r0;
            *(float4*)&g_k[b][n][4] = r1;
        } else {
            int c0 = o0 - 16;
            *(float4*)&g_v[b][n][c0]     = r0;
            *(float4*)&g_v[b][n][c0 + 4] = r1;
        }
    }
}

// ---------------------------------------------------------------------
// Kernel 2: Z_n = sum_m exp(q_n . k_m); then v[n][:] *= 1/Z_n (in place).
// 128 threads = 128 rows n per block.
// ---------------------------------------------------------------------
__global__ void __launch_bounds__(128) k_rowsum()
{
    __shared__ float ks[MT][CQ];         // 4 KB k tile
    int t = threadIdx.x, bid = blockIdx.x;
    int b = bid / (NN / 128);
    int n = (bid % (NN / 128)) * 128 + t;

    float q[8];
    {
        float4 qa = *(const float4*)&g_q[b][n][0];
        float4 qb = *(const float4*)&g_q[b][n][4];
        q[0] = qa.x; q[1] = qa.y; q[2] = qa.z; q[3] = qa.w;
        q[4] = qb.x; q[5] = qb.y; q[6] = qb.z; q[7] = qb.w;
    }

    float Z = 0.0f;
    for (int mt = 0; mt < NN; mt += MT) {
        __syncthreads();
        const float4* src = (const float4*)&g_k[b][mt][0];
        ((float4*)ks)[t]       = src[t];
        ((float4*)ks)[t + 128] = src[t + 128];
        __syncthreads();
#pragma unroll 4
        for (int m = 0; m < MT; m++) {
            float4 ka = *(const float4*)&ks[m][0];   // broadcast
            float4 kb = *(const float4*)&ks[m][4];
            float s = q[0] * ka.x;
            s = fmaf(q[1], ka.y, s);
            s = fmaf(q[2], ka.z, s);
            s = fmaf(q[3], ka.w, s);
            s = fmaf(q[4], kb.x, s);
            s = fmaf(q[5], kb.y, s);
            s = fmaf(q[6], kb.z, s);
            s = fmaf(q[7], kb.w, s);
            Z += __expf(s);
        }
    }
    float rz = 1.0f / Z;
    float4* vp = (float4*)&g_v[b][n][0];
#pragma unroll
    for (int i = 0; i < 16; i++) {
        float4 v = vp[i];
        v.x *= rz; v.y *= rz; v.z *= rz; v.w *= rz;
        vp[i] = v;
    }
}

// ---------------------------------------------------------------------
// Kernel 3 (hot): att tile [64][128] per block.
//   phase A: E[n][m] = exp(q_n . k_m) into SMEM (k in registers per m)
//   phase B: acc[c][m] += (v/Z)[c][n] * E[n][m]   (8x4 micro-tiles, FFMA2)
// ---------------------------------------------------------------------
__global__ void __launch_bounds__(256) k_attn()
{
    __shared__ float es[NT][MT];   // 24 KB exp tile
    __shared__ float ws[NT][CC];   // 12 KB scaled-v tile (row-major [n][c])
    __shared__ float qs[NT][CQ];   // 1.5 KB q tile

    int t = threadIdx.x, bid = blockIdx.x;
    int b  = bid / (NN / MT);
    int m0 = (bid % (NN / MT)) * MT;

    // phase A identity: column ma, starting row arow
    int ma   = t & (MT - 1);
    int arow = t >> 7;
    float kr[8];
    {
        float4 ka = *(const float4*)&g_k[b][m0 + ma][0];
        float4 kb = *(const float4*)&g_k[b][m0 + ma][4];
        kr[0] = ka.x; kr[1] = ka.y; kr[2] = ka.z; kr[3] = ka.w;
        kr[4] = kb.x; kr[5] = kb.y; kr[6] = kb.z; kr[7] = kb.w;
    }

    // phase B identity: 8 channels x 4 columns micro-tile
    int m4 = (t & 31) * 4;
    int c8 = (t >> 5) * 8;

    unsigned long long acc[8][2];
#pragma unroll
    for (int j = 0; j < 8; j++) { acc[j][0] = 0ull; acc[j][1] = 0ull; }

    for (int nt = 0; nt < NN; nt += NT) {
        __syncthreads();                       // protect es/ws from prior readers
        if (t < NT * 2)                        // 96 float4 = qs tile
            ((float4*)qs)[t] = ((const float4*)&g_q[b][nt][0])[t];
        {
            const float4* wsrc = (const float4*)&g_v[b][nt][0];  // 768 float4
            float4* wdst = (float4*)ws;
#pragma unroll
            for (int i = 0; i < 3; i++) wdst[t + i * 256] = wsrc[t + i * 256];
        }
        __syncthreads();

        // ---- phase A: 24 rows per thread ----
#pragma unroll
        for (int i = 0; i < NT / 2; i++) {
            int n = arow + 2 * i;
            float4 qa = *(const float4*)&qs[n][0];   // broadcast
            float4 qb = *(const float4*)&qs[n][4];
            float s = qa.x * kr[0];
            s = fmaf(qa.y, kr[1], s);
            s = fmaf(qa.z, kr[2], s);
            s = fmaf(qa.w, kr[3], s);
            s = fmaf(qb.x, kr[4], s);
            s = fmaf(qb.y, kr[5], s);
            s = fmaf(qb.z, kr[6], s);
            s = fmaf(qb.w, kr[7], s);
            es[n][ma] = __expf(s);
        }
        __syncthreads();

        // ---- phase B: register-blocked GEMM with packed FFMA2 ----
#pragma unroll 4
        for (int n = 0; n < NT; n++) {
            float4 e  = *(const float4*)&es[n][m4];
            float4 w0 = *(const float4*)&ws[n][c8];       // broadcast
            float4 w1 = *(const float4*)&ws[n][c8 + 4];   // broadcast
            unsigned long long e01 = pk2(e.x, e.y);
            unsigned long long e23 = pk2(e.z, e.w);
            unsigned long long wp;
            wp = pk2(w0.x, w0.x); acc[0][0] = ffma2(e01, wp, acc[0][0]); acc[0][1] = ffma2(e23, wp, acc[0][1]);
            wp = pk2(w0.y, w0.y); acc[1][0] = ffma2(e01, wp, acc[1][0]); acc[1][1] = ffma2(e23, wp, acc[1][1]);
            wp = pk2(w0.z, w0.z); acc[2][0] = ffma2(e01, wp, acc[2][0]); acc[2][1] = ffma2(e23, wp, acc[2][1]);
            wp = pk2(w0.w, w0.w); acc[3][0] = ffma2(e01, wp, acc[3][0]); acc[3][1] = ffma2(e23, wp, acc[3][1]);
            wp = pk2(w1.x, w1.x); acc[4][0] = ffma2(e01, wp, acc[4][0]); acc[4][1] = ffma2(e23, wp, acc[4][1]);
            wp = pk2(w1.y, w1.y); acc[5][0] = ffma2(e01, wp, acc[5][0]); acc[5][1] = ffma2(e23, wp, acc[5][1]);
            wp = pk2(w1.z, w1.z); acc[6][0] = ffma2(e01, wp, acc[6][0]); acc[6][1] = ffma2(e23, wp, acc[6][1]);
            wp = pk2(w1.w, w1.w); acc[7][0] = ffma2(e01, wp, acc[7][0]); acc[7][1] = ffma2(e23, wp, acc[7][1]);
        }
    }

    // write att tile, layout [b][c][m]
#pragma unroll
    for (int j = 0; j < 8; j++) {
        float a0, a1, a2, a3;
        upk2(acc[j][0], a0, a1);
        upk2(acc[j][1], a2, a3);
        float4 r = make_float4(a0, a1, a2, a3);
        *(float4*)&g_att[b][c8 + j][m0 + m4] = r;
    }
}

// ---------------------------------------------------------------------
// Kernel 4: out = wo @ att + bo  (1x1 conv), writes d_out [B][C][N].
// ---------------------------------------------------------------------
__global__ void __launch_bounds__(128) k_proj(
    const float* __restrict__ wo, const float* __restrict__ bo,
    float* __restrict__ out)
{
    __shared__ float WT[CC][CC];   // [c][o] = wo[o][c]
    __shared__ float bias[CC];
    int t = threadIdx.x;
    for (int idx = t; idx < CC * CC; idx += 128) {
        int c = idx / CC, o = idx % CC;
        WT[c][o] = wo[o * CC + c];
    }
    if (t < CC) bias[t] = bo[t];
    __syncthreads();

    int pix = blockIdx.x * 128 + t;
    int b = pix / NN, m = pix % NN;
    float xr[CC];
#pragma unroll
    for (int c = 0; c < CC; c++) xr[c] = g_att[b][c][m];   // coalesced per c

    for (int o0 = 0; o0 < CC; o0 += 8) {
        float acc[8];
#pragma unroll
        for (int j = 0; j < 8; j++) acc[j] = bias[o0 + j];
#pragma unroll 16
        for (int c = 0; c < CC; c++) {
            float4 wa = *(const float4*)&WT[c][o0];
            float4 wb = *(const float4*)&WT[c][o0 + 4];
            float xv = xr[c];
            acc[0] = fmaf(wa.x, xv, acc[0]);
            acc[1] = fmaf(wa.y, xv, acc[1]);
            acc[2] = fmaf(wa.z, xv, acc[2]);
            acc[3] = fmaf(wa.w, xv, acc[3]);
            acc[4] = fmaf(wb.x, xv, acc[4]);
            acc[5] = fmaf(wb.y, xv, acc[5]);
            acc[6] = fmaf(wb.z, xv, acc[6]);
            acc[7] = fmaf(wb.w, xv, acc[7]);
        }
#pragma unroll
        for (int j = 0; j < 8; j++)
            out[((size_t)b * CC + o0 + j) * NN + m] = acc[j];
    }
}

// ---------------------------------------------------------------------
extern "C" void kernel_launch(void* const* d_in, const int* in_sizes, int n_in,
                              void* d_out, int out_size)
{
    const float* x  = (const float*)d_in[0];
    const float* wq = (const float*)d_in[1];
    const float* bq = (const float*)d_in[2];
    const float* wk = (const float*)d_in[3];
    const float* bk = (const float*)d_in[4];
    const float* wv = (const float*)d_in[5];
    const float* bv = (const float*)d_in[6];
    const float* wo = (const float*)d_in[7];
    const float* bo = (const float*)d_in[8];
    float* out = (float*)d_out;

    k_qkv   <<<144, 128>>>(x, wq, bq, wk, bk, wv, bv);
    k_rowsum<<<144, 128>>>();
    k_attn  <<<144, 256>>>();
    k_proj  <<<144, 128>>>(wo, bo, out);
}